// round 1
// baseline (speedup 1.0000x reference)
#include <cuda_runtime.h>

#define NN 100000
#define EE 800000
#define HID 128

// ---------------- scratch (static device globals; no allocation) -------------
__device__ int   g_cnt[NN];
__device__ int   g_rowptr[NN + 1];
__device__ int   g_wptr[NN];
__device__ float g_dinv[NN];
__device__ int   g_colsrc[EE];
__device__ float g_h0[NN * 16];
__device__ float g_agg[NN * HID];
__device__ float g_emb[NN * HID];

// ---------------- graph preprocessing ----------------------------------------

// zero degree counts + build h0 = concat(x[:, :8], x_mask[:, :8])
__global__ void k_init(const float* __restrict__ x, const float* __restrict__ xm) {
    int i = blockIdx.x * blockDim.x + threadIdx.x;
    if (i < NN) {
        g_cnt[i] = 0;
#pragma unroll
        for (int c = 0; c < 8; c++) {
            g_h0[i * 16 + c]     = x[i * 10 + c];
            g_h0[i * 16 + 8 + c] = xm[i * 10 + c];
        }
    }
}

__global__ void k_count(const int* __restrict__ ei) {
    int e = blockIdx.x * blockDim.x + threadIdx.x;
    if (e < EE) atomicAdd(&g_cnt[ei[EE + e]], 1);
}

__global__ void k_dinv() {
    int v = blockIdx.x * blockDim.x + threadIdx.x;
    if (v < NN) g_dinv[v] = rsqrtf((float)g_cnt[v] + 1.0f);
}

// single-block exclusive scan of g_cnt -> g_rowptr (and copy to g_wptr)
__global__ void k_scan() {
    __shared__ int sdata[1024];
    __shared__ int carry;
    int t = threadIdx.x;
    if (t == 0) carry = 0;
    __syncthreads();
    for (int base = 0; base < NN; base += 1024) {
        int v = (base + t < NN) ? g_cnt[base + t] : 0;
        sdata[t] = v;
        __syncthreads();
#pragma unroll
        for (int off = 1; off < 1024; off <<= 1) {
            int x = (t >= off) ? sdata[t - off] : 0;
            __syncthreads();
            sdata[t] += x;
            __syncthreads();
        }
        int excl = sdata[t] - v;
        if (base + t < NN) {
            g_rowptr[base + t] = carry + excl;
            g_wptr[base + t]   = carry + excl;
        }
        __syncthreads();
        if (t == 1023) carry += sdata[1023];
        __syncthreads();
    }
    if (t == 0) g_rowptr[NN] = carry;
}

__global__ void k_fill(const int* __restrict__ ei) {
    int e = blockIdx.x * blockDim.x + threadIdx.x;
    if (e < EE) {
        int s = ei[e];
        int d = ei[EE + e];
        int p = atomicAdd(&g_wptr[d], 1);
        g_colsrc[p] = s;
    }
}

// ---------------- aggregation (gather over CSR) -------------------------------

// layer-0 aggregation: 16 channels, half-warp per node, no relu on input
__global__ void k_agg16() {
    int tid = blockIdx.x * blockDim.x + threadIdx.x;
    int v = tid >> 4;
    int c = tid & 15;
    if (v >= NN) return;
    float dv = g_dinv[v];
    float acc = g_h0[v * 16 + c] * dv * dv;
    int beg = g_rowptr[v], end = g_rowptr[v + 1];
    for (int e = beg; e < end; e++) {
        int u = g_colsrc[e];
        acc += g_h0[u * 16 + c] * (g_dinv[u] * dv);
    }
    g_agg[v * 16 + c] = acc;
}

// 128-channel aggregation with relu-on-read: warp per node, float4 per lane
__global__ void k_agg128(const float* __restrict__ hin) {
    int w = (blockIdx.x * blockDim.x + threadIdx.x) >> 5;
    if (w >= NN) return;
    int lane = threadIdx.x & 31;
    float dv = g_dinv[w];
    float4 h = *(const float4*)(hin + w * HID + lane * 4);
    h.x = fmaxf(h.x, 0.f); h.y = fmaxf(h.y, 0.f);
    h.z = fmaxf(h.z, 0.f); h.w = fmaxf(h.w, 0.f);
    float sw = dv * dv;
    float4 acc = make_float4(h.x * sw, h.y * sw, h.z * sw, h.w * sw);
    int beg = g_rowptr[w], end = g_rowptr[w + 1];
    for (int e = beg; e < end; e++) {
        int u = g_colsrc[e];
        float wgt = g_dinv[u] * dv;
        float4 hu = *(const float4*)(hin + u * HID + lane * 4);
        hu.x = fmaxf(hu.x, 0.f); hu.y = fmaxf(hu.y, 0.f);
        hu.z = fmaxf(hu.z, 0.f); hu.w = fmaxf(hu.w, 0.f);
        acc.x += hu.x * wgt; acc.y += hu.y * wgt;
        acc.z += hu.z * wgt; acc.w += hu.w * wgt;
    }
    *(float4*)(g_agg + w * HID + lane * 4) = acc;
}

// ---------------- GEMMs -------------------------------------------------------

// layer-0 GEMM: [N,16] @ [16,128] + b -> g_emb. 2 rows per 256-thread block.
__global__ void k_gemm0(const float* __restrict__ W0, const float* __restrict__ b0) {
    __shared__ float Ws[16 * 128];
    int t = threadIdx.x;
    for (int i = t; i < 16 * 128; i += 256) Ws[i] = W0[i];
    __syncthreads();
    int row = blockIdx.x * 2 + (t >> 7);
    int col = t & 127;
    float acc = b0[col];
#pragma unroll
    for (int k = 0; k < 16; k++)
        acc += g_agg[row * 16 + k] * Ws[k * 128 + col];
    g_emb[row * HID + col] = acc;
}

// generic [N,128] @ [128,128] + b GEMM, 128x128 block tile, 8x8 thread tile
__global__ void __launch_bounds__(256, 2)
k_gemm128(const float* __restrict__ in, const float* __restrict__ W,
          const float* __restrict__ bias, float* __restrict__ out,
          int relu_in, int relu_out) {
    __shared__ float As[128][17];
    __shared__ float Wt[16][128];
    int t  = threadIdx.x;
    int tx = t & 15, ty = t >> 4;
    int row0 = blockIdx.x * 128;

    float acc[8][8];
#pragma unroll
    for (int i = 0; i < 8; i++)
#pragma unroll
        for (int j = 0; j < 8; j++) acc[i][j] = 0.f;

    for (int kc = 0; kc < 128; kc += 16) {
        // load A tile: 128 rows x 16 k (512 float4, 2 per thread)
#pragma unroll
        for (int l = 0; l < 2; l++) {
            int idx = t + l * 256;
            int r = idx >> 2, q = idx & 3;
            int gr = row0 + r;
            float4 v = make_float4(0.f, 0.f, 0.f, 0.f);
            if (gr < NN) v = *(const float4*)(in + gr * HID + kc + q * 4);
            if (relu_in) {
                v.x = fmaxf(v.x, 0.f); v.y = fmaxf(v.y, 0.f);
                v.z = fmaxf(v.z, 0.f); v.w = fmaxf(v.w, 0.f);
            }
            As[r][q * 4 + 0] = v.x; As[r][q * 4 + 1] = v.y;
            As[r][q * 4 + 2] = v.z; As[r][q * 4 + 3] = v.w;
        }
        // load W tile: 16 k x 128 cols
#pragma unroll
        for (int l = 0; l < 2; l++) {
            int idx = t + l * 256;
            int k = idx >> 5, q = idx & 31;
            *(float4*)(&Wt[k][q * 4]) = *(const float4*)(W + (kc + k) * 128 + q * 4);
        }
        __syncthreads();
#pragma unroll
        for (int k = 0; k < 16; k++) {
            float a[8], b[8];
#pragma unroll
            for (int i = 0; i < 8; i++) a[i] = As[ty * 8 + i][k];
            float4 bv0 = *(float4*)(&Wt[k][tx * 8]);
            float4 bv1 = *(float4*)(&Wt[k][tx * 8 + 4]);
            b[0] = bv0.x; b[1] = bv0.y; b[2] = bv0.z; b[3] = bv0.w;
            b[4] = bv1.x; b[5] = bv1.y; b[6] = bv1.z; b[7] = bv1.w;
#pragma unroll
            for (int i = 0; i < 8; i++)
#pragma unroll
                for (int j = 0; j < 8; j++) acc[i][j] += a[i] * b[j];
        }
        __syncthreads();
    }

    float bj[8];
#pragma unroll
    for (int j = 0; j < 8; j++) bj[j] = bias[tx * 8 + j];
#pragma unroll
    for (int i = 0; i < 8; i++) {
        int gr = row0 + ty * 8 + i;
        if (gr < NN) {
            float4 o0, o1;
            float v0 = acc[i][0] + bj[0], v1 = acc[i][1] + bj[1];
            float v2 = acc[i][2] + bj[2], v3 = acc[i][3] + bj[3];
            float v4 = acc[i][4] + bj[4], v5 = acc[i][5] + bj[5];
            float v6 = acc[i][6] + bj[6], v7 = acc[i][7] + bj[7];
            if (relu_out) {
                v0 = fmaxf(v0, 0.f); v1 = fmaxf(v1, 0.f); v2 = fmaxf(v2, 0.f);
                v3 = fmaxf(v3, 0.f); v4 = fmaxf(v4, 0.f); v5 = fmaxf(v5, 0.f);
                v6 = fmaxf(v6, 0.f); v7 = fmaxf(v7, 0.f);
            }
            o0 = make_float4(v0, v1, v2, v3);
            o1 = make_float4(v4, v5, v6, v7);
            *(float4*)(out + gr * HID + tx * 8)     = o0;
            *(float4*)(out + gr * HID + tx * 8 + 4) = o1;
        }
    }
}

// final head: [N,128] @ [128,3] + b. One warp per row.
__global__ void k_gemm3(const float* __restrict__ in, const float* __restrict__ Wr2,
                        const float* __restrict__ br2, float* __restrict__ out) {
    __shared__ float Ws[128 * 3];
    int t = threadIdx.x;
    for (int i = t; i < 384; i += 256) Ws[i] = Wr2[i];
    __syncthreads();
    int v = (blockIdx.x * blockDim.x + t) >> 5;
    if (v >= NN) return;
    int lane = t & 31;
    float a0 = 0.f, a1 = 0.f, a2 = 0.f;
    for (int k = lane; k < 128; k += 32) {
        float h = in[v * HID + k];
        a0 += h * Ws[k * 3 + 0];
        a1 += h * Ws[k * 3 + 1];
        a2 += h * Ws[k * 3 + 2];
    }
#pragma unroll
    for (int off = 16; off > 0; off >>= 1) {
        a0 += __shfl_xor_sync(0xFFFFFFFF, a0, off);
        a1 += __shfl_xor_sync(0xFFFFFFFF, a1, off);
        a2 += __shfl_xor_sync(0xFFFFFFFF, a2, off);
    }
    if (lane == 0) {
        out[v * 3 + 0] = a0 + br2[0];
        out[v * 3 + 1] = a1 + br2[1];
        out[v * 3 + 2] = a2 + br2[2];
    }
}

// ---------------- launch ------------------------------------------------------

extern "C" void kernel_launch(void* const* d_in, const int* in_sizes, int n_in,
                              void* d_out, int out_size) {
    const float* x    = (const float*)d_in[0];
    const float* xm   = (const float*)d_in[1];
    const int*   ei   = (const int*)d_in[2];
    const float* W0   = (const float*)d_in[3];
    const float* b0   = (const float*)d_in[4];
    const float* Wh   = (const float*)d_in[5];
    const float* bh   = (const float*)d_in[6];
    const float* Wr1  = (const float*)d_in[7];
    const float* br1  = (const float*)d_in[8];
    const float* Wr2  = (const float*)d_in[9];
    const float* br2  = (const float*)d_in[10];
    float* out = (float*)d_out;
    float* out_emb  = out;             // [N,128]
    float* out_pred = out + NN * HID;  // [N,3]

    float* p_agg; cudaGetSymbolAddress((void**)&p_agg, g_agg);
    float* p_emb; cudaGetSymbolAddress((void**)&p_emb, g_emb);

    // graph preprocessing
    k_init<<<(NN + 255) / 256, 256>>>(x, xm);
    k_count<<<(EE + 255) / 256, 256>>>(ei);
    k_dinv<<<(NN + 255) / 256, 256>>>();
    k_scan<<<1, 1024>>>();
    k_fill<<<(EE + 255) / 256, 256>>>(ei);

    int gemm_blocks = (NN + 127) / 128;

    // layer 0: aggregate 16-dim, then GEMM to 128
    k_agg16<<<(NN * 16 + 255) / 256, 256>>>();
    k_gemm0<<<NN / 2, 256>>>(W0, b0);

    // hidden layers 0..3 (relu on aggregation read)
    for (int i = 0; i < 4; i++) {
        k_agg128<<<(NN * 32 + 255) / 256, 256>>>(p_emb);
        float* dst = (i == 3) ? out_emb : p_emb;
        k_gemm128<<<gemm_blocks, 256>>>(p_agg, Wh + i * 128 * 128, bh + i * 128,
                                        dst, 0, 0);
    }

    // head: t = relu(relu(emb) @ Wr1 + br1); pred = t @ Wr2 + br2
    k_gemm128<<<gemm_blocks, 256>>>(out_emb, Wr1, br1, p_emb, 1, 1);
    k_gemm3<<<(NN * 32 + 255) / 256, 256>>>(p_emb, Wr2, br2, out_pred);
}

// round 2
// speedup vs baseline: 1.3092x; 1.3092x over previous
#include <cuda_runtime.h>
#include <cuda_bf16.h>
#include <mma.h>

using namespace nvcuda;

#define NN 100000
#define EE 800000
#define HID 128
#define NB_SCAN 98   // ceil(NN/1024)

// ---------------- scratch (static device globals; no allocation) -------------
__device__ int   g_cnt[NN];
__device__ int   g_rowptr[NN + 1];
__device__ int   g_wptr[NN];
__device__ float g_dinv[NN];
__device__ int   g_colsrc[EE];
__device__ float g_h0[NN * 16];
__device__ float g_agg[NN * HID];
__device__ float g_emb[NN * HID];
__device__ int   g_bsum[128];
__device__ int   g_bsumx[128];
__device__ __nv_bfloat16 g_whi[5 * 128 * 128];  // Wh[0..3], Wr1 (hi)
__device__ __nv_bfloat16 g_wlo[5 * 128 * 128];  // (lo)

// ---------------- graph preprocessing ----------------------------------------

__global__ void k_init(const float* __restrict__ x, const float* __restrict__ xm) {
    int i = blockIdx.x * blockDim.x + threadIdx.x;
    if (i < NN) {
        g_cnt[i] = 0;
#pragma unroll
        for (int c = 0; c < 8; c++) {
            g_h0[i * 16 + c]     = x[i * 10 + c];
            g_h0[i * 16 + 8 + c] = xm[i * 10 + c];
        }
    }
}

__global__ void k_count(const int* __restrict__ ei) {
    int e = blockIdx.x * blockDim.x + threadIdx.x;
    if (e < EE) atomicAdd(&g_cnt[ei[EE + e]], 1);
}

// split weights into bf16 hi + lo (Wh[0..3] then Wr1)
__global__ void k_wsplit(const float* __restrict__ Wh, const float* __restrict__ Wr1) {
    int i = blockIdx.x * blockDim.x + threadIdx.x;
    if (i >= 5 * 128 * 128) return;
    float v = (i < 4 * 128 * 128) ? Wh[i] : Wr1[i - 4 * 128 * 128];
    __nv_bfloat16 hi = __float2bfloat16(v);
    g_whi[i] = hi;
    g_wlo[i] = __float2bfloat16(v - __bfloat162float(hi));
}

// pass 1: per-block exclusive scan; also compute dinv
__global__ void k_scan1() {
    __shared__ int sdata[1024];
    int t = threadIdx.x;
    int i = blockIdx.x * 1024 + t;
    int v = (i < NN) ? g_cnt[i] : 0;
    if (i < NN) g_dinv[i] = rsqrtf((float)v + 1.0f);
    sdata[t] = v;
    __syncthreads();
#pragma unroll
    for (int off = 1; off < 1024; off <<= 1) {
        int x = (t >= off) ? sdata[t - off] : 0;
        __syncthreads();
        sdata[t] += x;
        __syncthreads();
    }
    if (i < NN) {
        int excl = sdata[t] - v;
        g_rowptr[i] = excl;
        g_wptr[i]   = excl;
    }
    if (t == 1023) g_bsum[blockIdx.x] = sdata[1023];
}

// pass 2: scan the 98 block sums (one small block)
__global__ void k_scan2() {
    __shared__ int sdata[128];
    int t = threadIdx.x;
    int v = (t < NB_SCAN) ? g_bsum[t] : 0;
    sdata[t] = v;
    __syncthreads();
#pragma unroll
    for (int off = 1; off < 128; off <<= 1) {
        int x = (t >= off) ? sdata[t - off] : 0;
        __syncthreads();
        sdata[t] += x;
        __syncthreads();
    }
    if (t < NB_SCAN) g_bsumx[t] = sdata[t] - v;
}

// pass 3: add block offsets
__global__ void k_scan3() {
    int i = blockIdx.x * blockDim.x + threadIdx.x;
    if (i < NN) {
        int off = g_bsumx[i >> 10];
        g_rowptr[i] += off;
        g_wptr[i]   += off;
    }
    if (i == 0) g_rowptr[NN] = EE;
}

__global__ void k_fill(const int* __restrict__ ei) {
    int e = blockIdx.x * blockDim.x + threadIdx.x;
    if (e < EE) {
        int s = ei[e];
        int d = ei[EE + e];
        int p = atomicAdd(&g_wptr[d], 1);
        g_colsrc[p] = s;
    }
}

// ---------------- aggregation (gather over CSR) -------------------------------

__global__ void k_agg16() {
    int tid = blockIdx.x * blockDim.x + threadIdx.x;
    int v = tid >> 4;
    int c = tid & 15;
    if (v >= NN) return;
    float dv = g_dinv[v];
    float acc = g_h0[v * 16 + c] * dv * dv;
    int beg = g_rowptr[v], end = g_rowptr[v + 1];
    for (int e = beg; e < end; e++) {
        int u = g_colsrc[e];
        acc += g_h0[u * 16 + c] * (g_dinv[u] * dv);
    }
    g_agg[v * 16 + c] = acc;
}

// 128-channel aggregation with relu-on-read: warp per node, float4 per lane
__global__ void k_agg128(const float* __restrict__ hin) {
    int w = (blockIdx.x * blockDim.x + threadIdx.x) >> 5;
    if (w >= NN) return;
    int lane = threadIdx.x & 31;
    float dv = g_dinv[w];
    float4 h = *(const float4*)(hin + w * HID + lane * 4);
    h.x = fmaxf(h.x, 0.f); h.y = fmaxf(h.y, 0.f);
    h.z = fmaxf(h.z, 0.f); h.w = fmaxf(h.w, 0.f);
    float sw = dv * dv;
    float4 acc = make_float4(h.x * sw, h.y * sw, h.z * sw, h.w * sw);
    int beg = g_rowptr[w], end = g_rowptr[w + 1];
    for (int e = beg; e < end; e++) {
        int u = g_colsrc[e];
        float wgt = g_dinv[u] * dv;
        float4 hu = *(const float4*)(hin + u * HID + lane * 4);
        hu.x = fmaxf(hu.x, 0.f); hu.y = fmaxf(hu.y, 0.f);
        hu.z = fmaxf(hu.z, 0.f); hu.w = fmaxf(hu.w, 0.f);
        acc.x += hu.x * wgt; acc.y += hu.y * wgt;
        acc.z += hu.z * wgt; acc.w += hu.w * wgt;
    }
    *(float4*)(g_agg + w * HID + lane * 4) = acc;
}

// ---------------- GEMMs -------------------------------------------------------

// layer-0 GEMM: [N,16] @ [16,128] + b -> g_emb (FFMA, cheap)
__global__ void k_gemm0(const float* __restrict__ W0, const float* __restrict__ b0) {
    __shared__ float Ws[16 * 128];
    int t = threadIdx.x;
    for (int i = t; i < 16 * 128; i += 256) Ws[i] = W0[i];
    __syncthreads();
    int row = blockIdx.x * 2 + (t >> 7);
    int col = t & 127;
    float acc = b0[col];
#pragma unroll
    for (int k = 0; k < 16; k++)
        acc += g_agg[row * 16 + k] * Ws[k * 128 + col];
    g_emb[row * HID + col] = acc;
}

// tensor-core [N,128] @ [128,128] GEMM with bf16 hi/lo split (fp32-accurate).
// 256 threads = 8 warps; block tile 128 rows x 128 cols; K chunked by 32.
// warp grid: 4 row-groups (32 rows) x 2 col-groups (64 cols); 2x4 16x16 tiles per warp.
#define ALD 40
#define WLD 136
__global__ void __launch_bounds__(256, 1)
k_gemm_tc(const float* __restrict__ in, int widx, const float* __restrict__ bias,
          float* __restrict__ out, int relu_in, int relu_out) {
    __shared__ __nv_bfloat16 a_hi[128 * ALD];
    __shared__ __nv_bfloat16 a_lo[128 * ALD];
    __shared__ __nv_bfloat16 w_hi[32 * WLD];
    __shared__ __nv_bfloat16 w_lo[32 * WLD];
    __shared__ float scratch[8 * 256];

    int t = threadIdx.x;
    int warp = t >> 5;
    int lane = t & 31;
    int warp_r = warp & 3;   // 0..3 -> 32-row group
    int warp_c = warp >> 2;  // 0..1 -> 64-col group
    int row0 = blockIdx.x * 128;

    const __nv_bfloat16* Whi = g_whi + widx * 128 * 128;
    const __nv_bfloat16* Wlo = g_wlo + widx * 128 * 128;

    wmma::fragment<wmma::accumulator, 16, 16, 16, float> acc[2][4];
#pragma unroll
    for (int i = 0; i < 2; i++)
#pragma unroll
        for (int j = 0; j < 4; j++) wmma::fill_fragment(acc[i][j], 0.0f);

    for (int chunk = 0; chunk < 4; chunk++) {
        int kc = chunk * 32;
        // load A [128 x 32] fp32 -> split into bf16 hi/lo in smem
#pragma unroll
        for (int l = 0; l < 4; l++) {
            int idx = t + l * 256;           // 0..1023 float4 slots
            int r = idx >> 3, q = idx & 7;   // 8 float4 per row (32 floats)
            int gr = row0 + r;
            float4 v = make_float4(0.f, 0.f, 0.f, 0.f);
            if (gr < NN) v = *(const float4*)(in + gr * HID + kc + q * 4);
            if (relu_in) {
                v.x = fmaxf(v.x, 0.f); v.y = fmaxf(v.y, 0.f);
                v.z = fmaxf(v.z, 0.f); v.w = fmaxf(v.w, 0.f);
            }
            float vv[4] = {v.x, v.y, v.z, v.w};
#pragma unroll
            for (int q2 = 0; q2 < 4; q2++) {
                __nv_bfloat16 hi = __float2bfloat16(vv[q2]);
                a_hi[r * ALD + q * 4 + q2] = hi;
                a_lo[r * ALD + q * 4 + q2] =
                    __float2bfloat16(vv[q2] - __bfloat162float(hi));
            }
        }
        // load W chunk [32 x 128] bf16 hi/lo (vectorized: uint4 = 8 bf16)
#pragma unroll
        for (int l = 0; l < 2; l++) {
            int idx = t + l * 256;            // 0..511 uint4 slots
            int kr = idx >> 4, q = idx & 15;  // 16 uint4 per k-row
            uint4 vh = *(const uint4*)(Whi + (kc + kr) * 128 + q * 8);
            uint4 vl = *(const uint4*)(Wlo + (kc + kr) * 128 + q * 8);
            *(uint4*)(&w_hi[kr * WLD + q * 8]) = vh;
            *(uint4*)(&w_lo[kr * WLD + q * 8]) = vl;
        }
        __syncthreads();

#pragma unroll
        for (int ks = 0; ks < 2; ks++) {
            wmma::fragment<wmma::matrix_a, 16, 16, 16, __nv_bfloat16, wmma::row_major> ah[2], al[2];
            wmma::fragment<wmma::matrix_b, 16, 16, 16, __nv_bfloat16, wmma::row_major> bh[4], bl[4];
#pragma unroll
            for (int i = 0; i < 2; i++) {
                const __nv_bfloat16* pa = &a_hi[(warp_r * 32 + i * 16) * ALD + ks * 16];
                wmma::load_matrix_sync(ah[i], pa, ALD);
                const __nv_bfloat16* pl = &a_lo[(warp_r * 32 + i * 16) * ALD + ks * 16];
                wmma::load_matrix_sync(al[i], pl, ALD);
            }
#pragma unroll
            for (int j = 0; j < 4; j++) {
                const __nv_bfloat16* pb = &w_hi[(ks * 16) * WLD + warp_c * 64 + j * 16];
                wmma::load_matrix_sync(bh[j], pb, WLD);
                const __nv_bfloat16* pl = &w_lo[(ks * 16) * WLD + warp_c * 64 + j * 16];
                wmma::load_matrix_sync(bl[j], pl, WLD);
            }
#pragma unroll
            for (int i = 0; i < 2; i++)
#pragma unroll
                for (int j = 0; j < 4; j++) {
                    wmma::mma_sync(acc[i][j], ah[i], bh[j], acc[i][j]);
                    wmma::mma_sync(acc[i][j], ah[i], bl[j], acc[i][j]);
                    wmma::mma_sync(acc[i][j], al[i], bh[j], acc[i][j]);
                }
        }
        __syncthreads();
    }

    // epilogue: per-warp scratch, add bias, optional relu, bounds-guarded store
    float* sc = &scratch[warp * 256];
#pragma unroll
    for (int i = 0; i < 2; i++)
#pragma unroll
        for (int j = 0; j < 4; j++) {
            wmma::store_matrix_sync(sc, acc[i][j], 16, wmma::mem_row_major);
            __syncwarp();
#pragma unroll
            for (int e = 0; e < 8; e++) {
                int idx = lane + e * 32;
                int r = idx >> 4, c = idx & 15;
                int gr = row0 + warp_r * 32 + i * 16 + r;
                int gc = warp_c * 64 + j * 16 + c;
                if (gr < NN) {
                    float v = sc[idx] + __ldg(&bias[gc]);
                    if (relu_out) v = fmaxf(v, 0.f);
                    out[gr * HID + gc] = v;
                }
            }
            __syncwarp();
        }
}

// final head: [N,128] @ [128,3] + b. One warp per row.
__global__ void k_gemm3(const float* __restrict__ in, const float* __restrict__ Wr2,
                        const float* __restrict__ br2, float* __restrict__ out) {
    __shared__ float Ws[128 * 3];
    int t = threadIdx.x;
    for (int i = t; i < 384; i += 256) Ws[i] = Wr2[i];
    __syncthreads();
    int v = (blockIdx.x * blockDim.x + t) >> 5;
    if (v >= NN) return;
    int lane = t & 31;
    float a0 = 0.f, a1 = 0.f, a2 = 0.f;
    for (int k = lane; k < 128; k += 32) {
        float h = in[v * HID + k];
        a0 += h * Ws[k * 3 + 0];
        a1 += h * Ws[k * 3 + 1];
        a2 += h * Ws[k * 3 + 2];
    }
#pragma unroll
    for (int off = 16; off > 0; off >>= 1) {
        a0 += __shfl_xor_sync(0xFFFFFFFF, a0, off);
        a1 += __shfl_xor_sync(0xFFFFFFFF, a1, off);
        a2 += __shfl_xor_sync(0xFFFFFFFF, a2, off);
    }
    if (lane == 0) {
        out[v * 3 + 0] = a0 + br2[0];
        out[v * 3 + 1] = a1 + br2[1];
        out[v * 3 + 2] = a2 + br2[2];
    }
}

// ---------------- launch ------------------------------------------------------

extern "C" void kernel_launch(void* const* d_in, const int* in_sizes, int n_in,
                              void* d_out, int out_size) {
    const float* x    = (const float*)d_in[0];
    const float* xm   = (const float*)d_in[1];
    const int*   ei   = (const int*)d_in[2];
    const float* W0   = (const float*)d_in[3];
    const float* b0   = (const float*)d_in[4];
    const float* Wh   = (const float*)d_in[5];
    const float* bh   = (const float*)d_in[6];
    const float* Wr1  = (const float*)d_in[7];
    const float* br1  = (const float*)d_in[8];
    const float* Wr2  = (const float*)d_in[9];
    const float* br2  = (const float*)d_in[10];
    float* out = (float*)d_out;
    float* out_emb  = out;             // [N,128]
    float* out_pred = out + NN * HID;  // [N,3]

    float* p_agg; cudaGetSymbolAddress((void**)&p_agg, g_agg);
    float* p_emb; cudaGetSymbolAddress((void**)&p_emb, g_emb);

    // graph preprocessing + weight split
    k_init<<<(NN + 255) / 256, 256>>>(x, xm);
    k_count<<<(EE + 255) / 256, 256>>>(ei);
    k_wsplit<<<(5 * 128 * 128 + 255) / 256, 256>>>(Wh, Wr1);
    k_scan1<<<NB_SCAN, 1024>>>();
    k_scan2<<<1, 128>>>();
    k_scan3<<<(NN + 255) / 256, 256>>>();
    k_fill<<<(EE + 255) / 256, 256>>>(ei);

    int gemm_blocks = (NN + 127) / 128;

    // layer 0: aggregate 16-dim, then GEMM to 128
    k_agg16<<<(NN * 16 + 255) / 256, 256>>>();
    k_gemm0<<<NN / 2, 256>>>(W0, b0);

    // hidden layers 0..3 (relu applied on aggregation read)
    for (int i = 0; i < 4; i++) {
        k_agg128<<<(NN * 32 + 255) / 256, 256>>>(p_emb);
        float* dst = (i == 3) ? out_emb : p_emb;
        k_gemm_tc<<<gemm_blocks, 256>>>(p_agg, i, bh + i * 128, dst, 0, 0);
    }

    // head: t = relu(relu(emb) @ Wr1 + br1); pred = t @ Wr2 + br2
    k_gemm_tc<<<gemm_blocks, 256>>>(out_emb, 4, br1, p_emb, 1, 1);
    k_gemm3<<<(NN * 32 + 255) / 256, 256>>>(p_emb, Wr2, br2, out_pred);
}

// round 3
// speedup vs baseline: 1.4116x; 1.0782x over previous
#include <cuda_runtime.h>
#include <cuda_bf16.h>
#include <mma.h>

using namespace nvcuda;

#define NN 100000
#define EE 800000
#define HID 128
#define NB_SCAN 98   // ceil(NN/1024)

// ---------------- scratch (static device globals; no allocation) -------------
__device__ int   g_cnt[NN];
__device__ int   g_rowptr[NN + 1];
__device__ int   g_wptr[NN];
__device__ float g_dinv[NN];
__device__ int   g_colsrc[EE];
__device__ float g_h0[NN * 16];
__device__ float g_h0s[NN * 16];     // h0 * dinv (pre-scaled for gather)
__device__ float g_agg[NN * HID];
__device__ float g_hs[NN * HID];     // relu(h) * dinv (pre-scaled for gather)
__device__ float g_emb[NN * HID];
__device__ int   g_bsum[128];
__device__ int   g_bsumx[128];
__device__ __nv_bfloat16 g_whi[5 * 128 * 128];  // Wh[0..3], Wr1 (hi)
__device__ __nv_bfloat16 g_wlo[5 * 128 * 128];  // (lo)

// ---------------- graph preprocessing ----------------------------------------

__global__ void k_init(const float* __restrict__ x, const float* __restrict__ xm) {
    int i = blockIdx.x * blockDim.x + threadIdx.x;
    if (i < NN) {
        g_cnt[i] = 0;
#pragma unroll
        for (int c = 0; c < 8; c++) {
            g_h0[i * 16 + c]     = x[i * 10 + c];
            g_h0[i * 16 + 8 + c] = xm[i * 10 + c];
        }
    }
}

__global__ void k_count(const int* __restrict__ ei) {
    int e = blockIdx.x * blockDim.x + threadIdx.x;
    if (e < EE) atomicAdd(&g_cnt[ei[EE + e]], 1);
}

// split weights into bf16 hi + lo (Wh[0..3] then Wr1)
__global__ void k_wsplit(const float* __restrict__ Wh, const float* __restrict__ Wr1) {
    int i = blockIdx.x * blockDim.x + threadIdx.x;
    if (i >= 5 * 128 * 128) return;
    float v = (i < 4 * 128 * 128) ? Wh[i] : Wr1[i - 4 * 128 * 128];
    __nv_bfloat16 hi = __float2bfloat16(v);
    g_whi[i] = hi;
    g_wlo[i] = __float2bfloat16(v - __bfloat162float(hi));
}

// pass 1: per-block exclusive scan; also compute dinv
__global__ void k_scan1() {
    __shared__ int sdata[1024];
    int t = threadIdx.x;
    int i = blockIdx.x * 1024 + t;
    int v = (i < NN) ? g_cnt[i] : 0;
    if (i < NN) g_dinv[i] = rsqrtf((float)v + 1.0f);
    sdata[t] = v;
    __syncthreads();
#pragma unroll
    for (int off = 1; off < 1024; off <<= 1) {
        int x = (t >= off) ? sdata[t - off] : 0;
        __syncthreads();
        sdata[t] += x;
        __syncthreads();
    }
    if (i < NN) {
        int excl = sdata[t] - v;
        g_rowptr[i] = excl;
        g_wptr[i]   = excl;
    }
    if (t == 1023) g_bsum[blockIdx.x] = sdata[1023];
}

// pass 2: scan the 98 block sums
__global__ void k_scan2() {
    __shared__ int sdata[128];
    int t = threadIdx.x;
    int v = (t < NB_SCAN) ? g_bsum[t] : 0;
    sdata[t] = v;
    __syncthreads();
#pragma unroll
    for (int off = 1; off < 128; off <<= 1) {
        int x = (t >= off) ? sdata[t - off] : 0;
        __syncthreads();
        sdata[t] += x;
        __syncthreads();
    }
    if (t < NB_SCAN) g_bsumx[t] = sdata[t] - v;
}

// pass 3: add block offsets; also build h0s = h0 * dinv
__global__ void k_scan3() {
    int i = blockIdx.x * blockDim.x + threadIdx.x;
    if (i < NN) {
        int off = g_bsumx[i >> 10];
        g_rowptr[i] += off;
        g_wptr[i]   += off;
        float dv = g_dinv[i];
#pragma unroll
        for (int c = 0; c < 16; c++)
            g_h0s[i * 16 + c] = g_h0[i * 16 + c] * dv;
    }
    if (i == 0) g_rowptr[NN] = EE;
}

__global__ void k_fill(const int* __restrict__ ei) {
    int e = blockIdx.x * blockDim.x + threadIdx.x;
    if (e < EE) {
        int s = ei[e];
        int d = ei[EE + e];
        int p = atomicAdd(&g_wptr[d], 1);
        g_colsrc[p] = s;
    }
}

// ---------------- aggregation (gather over CSR, pre-scaled inputs) ------------

// layer-0: 16 channels, 16 lanes per node, unroll 4
__global__ void k_agg16() {
    int tid = blockIdx.x * blockDim.x + threadIdx.x;
    int v = tid >> 4;
    int c = tid & 15;
    if (v >= NN) return;
    float dv = g_dinv[v];
    float acc = g_h0s[v * 16 + c];
    int e = g_rowptr[v], end = g_rowptr[v + 1];
    for (; e + 4 <= end; e += 4) {
        int u0 = g_colsrc[e + 0];
        int u1 = g_colsrc[e + 1];
        int u2 = g_colsrc[e + 2];
        int u3 = g_colsrc[e + 3];
        float x0 = __ldg(g_h0s + u0 * 16 + c);
        float x1 = __ldg(g_h0s + u1 * 16 + c);
        float x2 = __ldg(g_h0s + u2 * 16 + c);
        float x3 = __ldg(g_h0s + u3 * 16 + c);
        acc += (x0 + x1) + (x2 + x3);
    }
    for (; e < end; e++) {
        int u = g_colsrc[e];
        acc += __ldg(g_h0s + u * 16 + c);
    }
    g_agg[v * 16 + c] = acc * dv;
}

// 128-channel: warp per node, float4 per lane, unroll 4 (MLP=4)
__global__ void __launch_bounds__(256) k_agg128() {
    int w = (blockIdx.x * blockDim.x + threadIdx.x) >> 5;
    if (w >= NN) return;
    int lane = threadIdx.x & 31;
    const float4* hp = (const float4*)g_hs;
    float dv = g_dinv[w];
    float4 s = __ldg(hp + w * 32 + lane);
    float ax = s.x, ay = s.y, az = s.z, aw = s.w;
    int e = g_rowptr[w], end = g_rowptr[w + 1];
    for (; e + 4 <= end; e += 4) {
        int u0 = g_colsrc[e + 0];
        int u1 = g_colsrc[e + 1];
        int u2 = g_colsrc[e + 2];
        int u3 = g_colsrc[e + 3];
        float4 x0 = __ldg(hp + u0 * 32 + lane);
        float4 x1 = __ldg(hp + u1 * 32 + lane);
        float4 x2 = __ldg(hp + u2 * 32 + lane);
        float4 x3 = __ldg(hp + u3 * 32 + lane);
        ax += (x0.x + x1.x) + (x2.x + x3.x);
        ay += (x0.y + x1.y) + (x2.y + x3.y);
        az += (x0.z + x1.z) + (x2.z + x3.z);
        aw += (x0.w + x1.w) + (x2.w + x3.w);
    }
    for (; e < end; e++) {
        int u = g_colsrc[e];
        float4 x = __ldg(hp + u * 32 + lane);
        ax += x.x; ay += x.y; az += x.z; aw += x.w;
    }
    float4 r = make_float4(ax * dv, ay * dv, az * dv, aw * dv);
    *((float4*)g_agg + w * 32 + lane) = r;
}

// ---------------- GEMMs -------------------------------------------------------

// layer-0 GEMM: [N,16] @ [16,128] + b -> hs = relu(out)*dinv
__global__ void k_gemm0(const float* __restrict__ W0, const float* __restrict__ b0) {
    __shared__ float Ws[16 * 128];
    int t = threadIdx.x;
    for (int i = t; i < 16 * 128; i += 256) Ws[i] = W0[i];
    __syncthreads();
    int row = blockIdx.x * 2 + (t >> 7);
    int col = t & 127;
    float acc = b0[col];
#pragma unroll
    for (int k = 0; k < 16; k++)
        acc += g_agg[row * 16 + k] * Ws[k * 128 + col];
    g_hs[row * HID + col] = fmaxf(acc, 0.f) * g_dinv[row];
}

// tensor-core [N,128]@[128,128] GEMM, bf16 hi/lo split, register-prefetch pipeline.
// emode: 0 = raw out, 1 = relu, 2 = relu * dinv[row]
#define ALD 40
#define WLD 136
__global__ void __launch_bounds__(256, 2)
k_gemm_tc(const float* __restrict__ in, int widx, const float* __restrict__ bias,
          float* __restrict__ out, int relu_in, int emode) {
    __shared__ __nv_bfloat16 a_hi[128 * ALD];
    __shared__ __nv_bfloat16 a_lo[128 * ALD];
    __shared__ __nv_bfloat16 w_hi[32 * WLD];
    __shared__ __nv_bfloat16 w_lo[32 * WLD];
    __shared__ float scratch[8 * 256];

    int t = threadIdx.x;
    int warp = t >> 5;
    int lane = t & 31;
    int warp_r = warp & 3;
    int warp_c = warp >> 2;
    int row0 = blockIdx.x * 128;

    const __nv_bfloat16* Whi = g_whi + widx * 128 * 128;
    const __nv_bfloat16* Wlo = g_wlo + widx * 128 * 128;

    // prefetch registers
    float4 va[4];
    uint4  vwh[2], vwl[2];

    auto load_chunk = [&](int kc) {
#pragma unroll
        for (int l = 0; l < 4; l++) {
            int idx = t + l * 256;
            int r = idx >> 3, q = idx & 7;
            int gr = row0 + r;
            float4 v = make_float4(0.f, 0.f, 0.f, 0.f);
            if (gr < NN) v = __ldg((const float4*)(in + gr * HID + kc + q * 4));
            va[l] = v;
        }
#pragma unroll
        for (int l = 0; l < 2; l++) {
            int idx = t + l * 256;
            int kr = idx >> 4, q = idx & 15;
            vwh[l] = __ldg((const uint4*)(Whi + (kc + kr) * 128 + q * 8));
            vwl[l] = __ldg((const uint4*)(Wlo + (kc + kr) * 128 + q * 8));
        }
    };
    auto store_chunk = [&]() {
#pragma unroll
        for (int l = 0; l < 4; l++) {
            int idx = t + l * 256;
            int r = idx >> 3, q = idx & 7;
            float vv[4] = {va[l].x, va[l].y, va[l].z, va[l].w};
#pragma unroll
            for (int q2 = 0; q2 < 4; q2++) {
                float f = relu_in ? fmaxf(vv[q2], 0.f) : vv[q2];
                __nv_bfloat16 hi = __float2bfloat16(f);
                a_hi[r * ALD + q * 4 + q2] = hi;
                a_lo[r * ALD + q * 4 + q2] =
                    __float2bfloat16(f - __bfloat162float(hi));
            }
        }
#pragma unroll
        for (int l = 0; l < 2; l++) {
            int idx = t + l * 256;
            int kr = idx >> 4, q = idx & 15;
            *(uint4*)(&w_hi[kr * WLD + q * 8]) = vwh[l];
            *(uint4*)(&w_lo[kr * WLD + q * 8]) = vwl[l];
        }
    };

    wmma::fragment<wmma::accumulator, 16, 16, 16, float> acc[2][4];
#pragma unroll
    for (int i = 0; i < 2; i++)
#pragma unroll
        for (int j = 0; j < 4; j++) wmma::fill_fragment(acc[i][j], 0.0f);

    load_chunk(0);
    store_chunk();
    __syncthreads();

    for (int chunk = 0; chunk < 4; chunk++) {
        if (chunk < 3) load_chunk((chunk + 1) * 32);  // LDG in flight during MMA
#pragma unroll
        for (int ks = 0; ks < 2; ks++) {
            wmma::fragment<wmma::matrix_a, 16, 16, 16, __nv_bfloat16, wmma::row_major> ah[2], al[2];
            wmma::fragment<wmma::matrix_b, 16, 16, 16, __nv_bfloat16, wmma::row_major> bh[4], bl[4];
#pragma unroll
            for (int i = 0; i < 2; i++) {
                wmma::load_matrix_sync(ah[i], &a_hi[(warp_r * 32 + i * 16) * ALD + ks * 16], ALD);
                wmma::load_matrix_sync(al[i], &a_lo[(warp_r * 32 + i * 16) * ALD + ks * 16], ALD);
            }
#pragma unroll
            for (int j = 0; j < 4; j++) {
                wmma::load_matrix_sync(bh[j], &w_hi[(ks * 16) * WLD + warp_c * 64 + j * 16], WLD);
                wmma::load_matrix_sync(bl[j], &w_lo[(ks * 16) * WLD + warp_c * 64 + j * 16], WLD);
            }
#pragma unroll
            for (int i = 0; i < 2; i++)
#pragma unroll
                for (int j = 0; j < 4; j++) {
                    wmma::mma_sync(acc[i][j], ah[i], bh[j], acc[i][j]);
                    wmma::mma_sync(acc[i][j], ah[i], bl[j], acc[i][j]);
                    wmma::mma_sync(acc[i][j], al[i], bh[j], acc[i][j]);
                }
        }
        __syncthreads();
        if (chunk < 3) {
            store_chunk();
            __syncthreads();
        }
    }

    // epilogue
    float* sc = &scratch[warp * 256];
#pragma unroll
    for (int i = 0; i < 2; i++)
#pragma unroll
        for (int j = 0; j < 4; j++) {
            wmma::store_matrix_sync(sc, acc[i][j], 16, wmma::mem_row_major);
            __syncwarp();
#pragma unroll
            for (int e = 0; e < 8; e++) {
                int idx = lane + e * 32;
                int r = idx >> 4, c = idx & 15;
                int gr = row0 + warp_r * 32 + i * 16 + r;
                int gc = warp_c * 64 + j * 16 + c;
                if (gr < NN) {
                    float v = sc[idx] + __ldg(&bias[gc]);
                    if (emode >= 1) v = fmaxf(v, 0.f);
                    if (emode == 2) v *= __ldg(&g_dinv[gr]);
                    out[gr * HID + gc] = v;
                }
            }
            __syncwarp();
        }
}

// final head: [N,128] @ [128,3] + b. One warp per row.
__global__ void k_gemm3(const float* __restrict__ in, const float* __restrict__ Wr2,
                        const float* __restrict__ br2, float* __restrict__ out) {
    __shared__ float Ws[128 * 3];
    int t = threadIdx.x;
    for (int i = t; i < 384; i += 256) Ws[i] = Wr2[i];
    __syncthreads();
    int v = (blockIdx.x * blockDim.x + t) >> 5;
    if (v >= NN) return;
    int lane = t & 31;
    float a0 = 0.f, a1 = 0.f, a2 = 0.f;
    for (int k = lane; k < 128; k += 32) {
        float h = in[v * HID + k];
        a0 += h * Ws[k * 3 + 0];
        a1 += h * Ws[k * 3 + 1];
        a2 += h * Ws[k * 3 + 2];
    }
#pragma unroll
    for (int off = 16; off > 0; off >>= 1) {
        a0 += __shfl_xor_sync(0xFFFFFFFF, a0, off);
        a1 += __shfl_xor_sync(0xFFFFFFFF, a1, off);
        a2 += __shfl_xor_sync(0xFFFFFFFF, a2, off);
    }
    if (lane == 0) {
        out[v * 3 + 0] = a0 + br2[0];
        out[v * 3 + 1] = a1 + br2[1];
        out[v * 3 + 2] = a2 + br2[2];
    }
}

// ---------------- launch ------------------------------------------------------

extern "C" void kernel_launch(void* const* d_in, const int* in_sizes, int n_in,
                              void* d_out, int out_size) {
    const float* x    = (const float*)d_in[0];
    const float* xm   = (const float*)d_in[1];
    const int*   ei   = (const int*)d_in[2];
    const float* W0   = (const float*)d_in[3];
    const float* b0   = (const float*)d_in[4];
    const float* Wh   = (const float*)d_in[5];
    const float* bh   = (const float*)d_in[6];
    const float* Wr1  = (const float*)d_in[7];
    const float* br1  = (const float*)d_in[8];
    const float* Wr2  = (const float*)d_in[9];
    const float* br2  = (const float*)d_in[10];
    float* out = (float*)d_out;
    float* out_emb  = out;             // [N,128]
    float* out_pred = out + NN * HID;  // [N,3]

    float* p_agg; cudaGetSymbolAddress((void**)&p_agg, g_agg);
    float* p_hs;  cudaGetSymbolAddress((void**)&p_hs,  g_hs);
    float* p_emb; cudaGetSymbolAddress((void**)&p_emb, g_emb);

    // graph preprocessing + weight split
    k_init<<<(NN + 255) / 256, 256>>>(x, xm);
    k_count<<<(EE + 255) / 256, 256>>>(ei);
    k_wsplit<<<(5 * 128 * 128 + 255) / 256, 256>>>(Wh, Wr1);
    k_scan1<<<NB_SCAN, 1024>>>();
    k_scan2<<<1, 128>>>();
    k_scan3<<<(NN + 255) / 256, 256>>>();
    k_fill<<<(EE + 255) / 256, 256>>>(ei);

    int gemm_blocks = (NN + 127) / 128;

    // layer 0: aggregate 16-dim, then GEMM to 128 (writes hs = relu*dinv)
    k_agg16<<<(NN * 16 + 255) / 256, 256>>>();
    k_gemm0<<<NN / 2, 256>>>(W0, b0);

    // hidden layers 0..3
    for (int i = 0; i < 4; i++) {
        k_agg128<<<(NN * 32 + 255) / 256, 256>>>();
        float* dst   = (i == 3) ? out_emb : p_hs;
        int    emode = (i == 3) ? 0 : 2;
        k_gemm_tc<<<gemm_blocks, 256>>>(p_agg, i, bh + i * 128, dst, 0, emode);
    }

    // head: t = relu(relu(emb) @ Wr1 + br1); pred = t @ Wr2 + br2
    k_gemm_tc<<<gemm_blocks, 256>>>(out_emb, 4, br1, p_emb, 1, 1);
    k_gemm3<<<(NN * 32 + 255) / 256, 256>>>(p_emb, Wr2, br2, out_pred);
}